// round 6
// baseline (speedup 1.0000x reference)
#include <cuda_runtime.h>
#include <cstdint>

// Fixed problem sizes: N=100000 nodes, E=1600000 edges, d=128.
#define NMAX 100000
#define EMAX 1600000
#define D    128

// Scratch (device globals — no allocations allowed)
__device__ float g_dinv[NMAX];            // rsqrt(in_degree + 1)
__device__ int   g_deg[NMAX];             // in-degree (real edges only)
__device__ int   g_fill[NMAX];            // scatter fill counters
__device__ int   g_rowptr[NMAX + 1];      // CSR row pointers (by dst)
__device__ int   g_srcs[EMAX];            // CSR column indices (src of each edge)
__device__ float g_h[(size_t)NMAX * D];   // GEMM output (messages)
__device__ float g_a[(size_t)NMAX * D];   // aggregation output

// ---------------------------------------------------------------------------
// packed f32x2 helpers (sm_100+)
// ---------------------------------------------------------------------------
__device__ __forceinline__ unsigned long long pk2(float lo, float hi) {
    unsigned long long r;
    asm("mov.b64 %0, {%1,%2};" : "=l"(r) : "f"(lo), "f"(hi));
    return r;
}
__device__ __forceinline__ unsigned long long fma2(unsigned long long a,
                                                   unsigned long long b,
                                                   unsigned long long c) {
    unsigned long long d;
    asm("fma.rn.f32x2 %0, %1, %2, %3;" : "=l"(d) : "l"(a), "l"(b), "l"(c));
    return d;
}
__device__ __forceinline__ float2 upk2(unsigned long long v) {
    float2 f;
    asm("mov.b64 {%0,%1}, %2;" : "=f"(f.x), "=f"(f.y) : "l"(v));
    return f;
}

// ---------------------------------------------------------------------------
// CSR build: zero -> degree histogram -> exclusive scan -> dinv -> scatter
// ---------------------------------------------------------------------------
__global__ void zero_counts(int n) {
    int i = blockIdx.x * blockDim.x + threadIdx.x;
    if (i < n) { g_deg[i] = 0; g_fill[i] = 0; }
}

__global__ void deg_hist(const int* __restrict__ dst, int e) {
    int i = blockIdx.x * blockDim.x + threadIdx.x;
    if (i < e) atomicAdd(&g_deg[dst[i]], 1);
}

// single block, 1024 threads: exclusive scan of g_deg -> g_rowptr
__global__ void scan_rowptr(int n) {
    __shared__ int wsum[32];
    __shared__ int carry;
    int tid = threadIdx.x;
    if (tid == 0) carry = 0;
    __syncthreads();
    for (int base = 0; base < n; base += 1024) {
        int i = base + tid;
        int v = (i < n) ? g_deg[i] : 0;
        int x = v;
#pragma unroll
        for (int o = 1; o < 32; o <<= 1) {
            int t = __shfl_up_sync(0xffffffffu, x, o);
            if ((tid & 31) >= o) x += t;
        }
        if ((tid & 31) == 31) wsum[tid >> 5] = x;
        __syncthreads();
        if (tid < 32) {
            int y = wsum[tid];
#pragma unroll
            for (int o = 1; o < 32; o <<= 1) {
                int t = __shfl_up_sync(0xffffffffu, y, o);
                if (tid >= o) y += t;
            }
            wsum[tid] = y;
        }
        __syncthreads();
        int incl = x + ((tid >= 32) ? wsum[(tid >> 5) - 1] : 0);
        int c = carry;
        if (i < n) g_rowptr[i] = c + incl - v;  // exclusive
        __syncthreads();
        if (tid == 0) carry = c + wsum[31];
        __syncthreads();  // protect wsum[31]/carry from next iteration
    }
    if (tid == 0) g_rowptr[n] = carry;
}

__global__ void dinv_compute(int n) {
    int i = blockIdx.x * blockDim.x + threadIdx.x;
    if (i < n) g_dinv[i] = rsqrtf((float)g_deg[i] + 1.0f);  // +1 self-loop
}

__global__ void scatter_edges(const int* __restrict__ src, const int* __restrict__ dst, int e) {
    int i = blockIdx.x * blockDim.x + threadIdx.x;
    if (i < e) {
        int d = dst[i];
        int pos = g_rowptr[d] + atomicAdd(&g_fill[d], 1);
        g_srcs[pos] = src[i];
    }
}

// ---------------------------------------------------------------------------
// GEMM: C[N,128] = A[N,128] @ W[128,128]   (packed f32x2 FMAs)
// 256 threads / 64 rows per block. W (64KB) + A tile (32KB) in dynamic smem.
// Thread: lane -> 4 consecutive cols, tid>>5 -> row slot; 8 rows x 4 cols.
// ---------------------------------------------------------------------------
__global__ void gemm128(const float* __restrict__ A, const float* __restrict__ W,
                        float* __restrict__ C, int n) {
    extern __shared__ float sm[];
    float* sW = sm;             // 128*128
    float* sA = sm + 128 * 128; // 64*128

    int tid = threadIdx.x;
    const float4* W4 = reinterpret_cast<const float4*>(W);
    float4* sW4 = reinterpret_cast<float4*>(sW);
#pragma unroll
    for (int i = 0; i < 16; i++) sW4[tid + 256 * i] = W4[tid + 256 * i];

    int row0 = blockIdx.x * 64;
    int nrows = n - row0; if (nrows > 64) nrows = 64;
    const float4* A4 = reinterpret_cast<const float4*>(A + (size_t)row0 * D);
    float4* sA4 = reinterpret_cast<float4*>(sA);
    for (int i = tid; i < nrows * 32; i += 256) sA4[i] = A4[i];
    __syncthreads();

    int lane = tid & 31;
    int rbase = tid >> 5;  // 0..7

    unsigned long long acc0[8], acc1[8];
#pragma unroll
    for (int r = 0; r < 8; r++) { acc0[r] = 0ull; acc1[r] = 0ull; }

#pragma unroll 4
    for (int k = 0; k < 128; k++) {
        float4 w = sW4[k * 32 + lane];
        unsigned long long wxy = pk2(w.x, w.y);
        unsigned long long wzw = pk2(w.z, w.w);
#pragma unroll
        for (int r = 0; r < 8; r++) {
            float a = sA[(rbase + r * 8) * 128 + k];  // warp-uniform broadcast
            unsigned long long aa = pk2(a, a);
            acc0[r] = fma2(aa, wxy, acc0[r]);
            acc1[r] = fma2(aa, wzw, acc1[r]);
        }
    }

    float4* C4 = reinterpret_cast<float4*>(C);
#pragma unroll
    for (int r = 0; r < 8; r++) {
        int rr = rbase + r * 8;
        if (rr < nrows) {
            float2 p0 = upk2(acc0[r]);
            float2 p1 = upk2(acc1[r]);
            float4 v; v.x = p0.x; v.y = p0.y; v.z = p1.x; v.w = p1.y;
            C4[(size_t)(row0 + rr) * 32 + lane] = v;
        }
    }
}

// ---------------------------------------------------------------------------
// CSR aggregation, fully fused:
//   a[v] = relu?( dinv[v] * sum_{s in N(v)} dinv[s]*h[s] + dinv[v]^2*h[v] + b )
// One warp per destination node; lane handles one float4 (4 of 128 cols).
// ---------------------------------------------------------------------------
__global__ void agg_csr(const float* __restrict__ bias, int n, int relu) {
    int v = (blockIdx.x * blockDim.x + threadIdx.x) >> 5;
    int lane = threadIdx.x & 31;
    if (v >= n) return;
    int beg = g_rowptr[v];
    int end = g_rowptr[v + 1];
    const float4* h4 = reinterpret_cast<const float4*>(g_h);

    float4 acc; acc.x = 0.f; acc.y = 0.f; acc.z = 0.f; acc.w = 0.f;
    for (int j = beg; j < end; j++) {
        int s = __ldg(&g_srcs[j]);
        float ws = __ldg(&g_dinv[s]);
        float4 hv = h4[(size_t)s * 32 + lane];
        acc.x += ws * hv.x; acc.y += ws * hv.y;
        acc.z += ws * hv.z; acc.w += ws * hv.w;
    }

    float dv = g_dinv[v];
    float ss = dv * dv;
    float4 hs = h4[(size_t)v * 32 + lane];
    float4 bb = reinterpret_cast<const float4*>(bias)[lane];
    acc.x = dv * acc.x + ss * hs.x + bb.x;
    acc.y = dv * acc.y + ss * hs.y + bb.y;
    acc.z = dv * acc.z + ss * hs.z + bb.z;
    acc.w = dv * acc.w + ss * hs.w + bb.w;
    if (relu) {
        acc.x = fmaxf(acc.x, 0.f); acc.y = fmaxf(acc.y, 0.f);
        acc.z = fmaxf(acc.z, 0.f); acc.w = fmaxf(acc.w, 0.f);
    }
    reinterpret_cast<float4*>(g_a)[(size_t)v * 32 + lane] = acc;
}

// ---------------------------------------------------------------------------
// Output GEMM: out[N,40] = g_a[N,128] @ Wout[128,40] + bout
// ---------------------------------------------------------------------------
__global__ void gemm_out(const float* __restrict__ W, const float* __restrict__ b,
                         float* __restrict__ C, int n) {
    __shared__ float sW[128 * 40];
    __shared__ float sb[40];
    int tid = threadIdx.x;
    for (int i = tid; i < 128 * 40; i += blockDim.x) sW[i] = W[i];
    if (tid < 40) sb[tid] = b[tid];
    __syncthreads();

    int idx = blockIdx.x * blockDim.x + tid;
    if (idx >= n * 40) return;
    int row = idx / 40;
    int j = idx - row * 40;
    const float4* a4 = reinterpret_cast<const float4*>(g_a) + (size_t)row * 32;
    float acc = sb[j];
#pragma unroll 8
    for (int k4 = 0; k4 < 32; k4++) {
        float4 av = a4[k4];
        int kb = k4 * 4;
        acc += av.x * sW[(kb + 0) * 40 + j];
        acc += av.y * sW[(kb + 1) * 40 + j];
        acc += av.z * sW[(kb + 2) * 40 + j];
        acc += av.w * sW[(kb + 3) * 40 + j];
    }
    C[idx] = acc;
}

// ---------------------------------------------------------------------------
// launch
// ---------------------------------------------------------------------------
extern "C" void kernel_launch(void* const* d_in, const int* in_sizes, int n_in,
                              void* d_out, int out_size) {
    const float* x    = (const float*)d_in[0];
    const int*   ei   = (const int*)d_in[1];
    const float* W1   = (const float*)d_in[2];
    const float* b1   = (const float*)d_in[3];
    const float* W2   = (const float*)d_in[4];
    const float* b2   = (const float*)d_in[5];
    const float* Wout = (const float*)d_in[6];
    const float* bout = (const float*)d_in[7];
    float* out = (float*)d_out;

    int n = in_sizes[0] / D;   // 100000
    int e = in_sizes[1] / 2;   // 1600000
    const int* src = ei;
    const int* dst = ei + e;

    static bool attr_set = false;
    if (!attr_set) {
        cudaFuncSetAttribute(gemm128, cudaFuncAttributeMaxDynamicSharedMemorySize,
                             (128 * 128 + 64 * 128) * (int)sizeof(float));
        attr_set = true;
    }
    const int smem_gemm = (128 * 128 + 64 * 128) * (int)sizeof(float);

    float* g_h_ptr; cudaGetSymbolAddress((void**)&g_h_ptr, g_h);
    float* g_a_ptr; cudaGetSymbolAddress((void**)&g_a_ptr, g_a);

    const int tb = 256;
    int nb_n = (n + tb - 1) / tb;
    int nb_e = (e + tb - 1) / tb;
    int gemm_blocks = (n + 63) / 64;
    int agg_blocks  = (n + 7) / 8;   // 8 warps (nodes) per block

    // ---- CSR build (reused by both layers) ----
    zero_counts<<<nb_n, tb>>>(n);
    deg_hist<<<nb_e, tb>>>(dst, e);
    scan_rowptr<<<1, 1024>>>(n);
    dinv_compute<<<nb_n, tb>>>(n);
    scatter_edges<<<nb_e, tb>>>(src, dst, e);

    // ---- layer 1: h = x@W1 ; a = relu(Ahat h + b1) ----
    gemm128<<<gemm_blocks, tb, smem_gemm>>>(x, W1, g_h_ptr, n);
    agg_csr<<<agg_blocks, tb>>>(b1, n, 1);

    // ---- layer 2: h = a@W2 ; a = Ahat h + b2 ----
    gemm128<<<gemm_blocks, tb, smem_gemm>>>(g_a_ptr, W2, g_h_ptr, n);
    agg_csr<<<agg_blocks, tb>>>(b2, n, 0);

    // ---- output: out = a@Wout + bout ----
    gemm_out<<<(n * 40 + tb - 1) / tb, tb>>>(Wout, bout, out, n);
}

// round 7
// speedup vs baseline: 1.4213x; 1.4213x over previous
#include <cuda_runtime.h>
#include <cstdint>

// Fixed problem sizes: N=100000 nodes, E=1600000 edges, d=128.
#define NMAX 100000
#define EMAX 1600000
#define D    128

// Scratch (device globals — no allocations allowed)
__device__ float g_dinv[NMAX];            // rsqrt(in_degree + 1)
__device__ int   g_deg[NMAX];             // in-degree (real edges only)
__device__ int   g_fill[NMAX];            // scatter fill counters (seeded = rowptr)
__device__ int   g_rowptr[NMAX + 1];      // CSR row pointers (by dst)
__device__ int   g_srcs[EMAX];            // CSR column indices (src of each edge)
__device__ float g_h[(size_t)NMAX * D];   // GEMM output (messages)
__device__ float g_a[(size_t)NMAX * D];   // aggregation output

// ---------------------------------------------------------------------------
// packed f32x2 helpers (sm_100+)
// ---------------------------------------------------------------------------
__device__ __forceinline__ unsigned long long pk2(float lo, float hi) {
    unsigned long long r;
    asm("mov.b64 %0, {%1,%2};" : "=l"(r) : "f"(lo), "f"(hi));
    return r;
}
__device__ __forceinline__ unsigned long long fma2(unsigned long long a,
                                                   unsigned long long b,
                                                   unsigned long long c) {
    unsigned long long d;
    asm("fma.rn.f32x2 %0, %1, %2, %3;" : "=l"(d) : "l"(a), "l"(b), "l"(c));
    return d;
}
__device__ __forceinline__ float2 upk2(unsigned long long v) {
    float2 f;
    asm("mov.b64 {%0,%1}, %2;" : "=f"(f.x), "=f"(f.y) : "l"(v));
    return f;
}

// ---------------------------------------------------------------------------
// CSR build
// ---------------------------------------------------------------------------
__global__ void zero_deg(int n) {
    int i = blockIdx.x * blockDim.x + threadIdx.x;
    if (i < n) g_deg[i] = 0;
}

__global__ void deg_hist(const int* __restrict__ dst, int e) {
    int i = blockIdx.x * blockDim.x + threadIdx.x;
    if (i < e) atomicAdd(&g_deg[dst[i]], 1);
}

// single block, 1024 threads: exclusive scan of g_deg -> g_rowptr.
// Fused: seeds g_fill with rowptr and computes g_dinv = rsqrt(deg+1).
__global__ void scan_rowptr(int n) {
    __shared__ int wsum[32];
    __shared__ int carry;
    int tid = threadIdx.x;
    if (tid == 0) carry = 0;
    __syncthreads();
    for (int base = 0; base < n; base += 1024) {
        int i = base + tid;
        int v = (i < n) ? g_deg[i] : 0;
        int x = v;
#pragma unroll
        for (int o = 1; o < 32; o <<= 1) {
            int t = __shfl_up_sync(0xffffffffu, x, o);
            if ((tid & 31) >= o) x += t;
        }
        if ((tid & 31) == 31) wsum[tid >> 5] = x;
        __syncthreads();
        if (tid < 32) {
            int y = wsum[tid];
#pragma unroll
            for (int o = 1; o < 32; o <<= 1) {
                int t = __shfl_up_sync(0xffffffffu, y, o);
                if (tid >= o) y += t;
            }
            wsum[tid] = y;
        }
        __syncthreads();
        int incl = x + ((tid >= 32) ? wsum[(tid >> 5) - 1] : 0);
        int c = carry;
        if (i < n) {
            int excl = c + incl - v;
            g_rowptr[i] = excl;
            g_fill[i]   = excl;                       // seed scatter counter
            g_dinv[i]   = rsqrtf((float)v + 1.0f);    // +1 self-loop
        }
        __syncthreads();
        if (tid == 0) carry = c + wsum[31];
        __syncthreads();  // protect wsum[31]/carry for next iteration
    }
    if (tid == 0) g_rowptr[n] = carry;
}

__global__ void scatter_edges(const int* __restrict__ src, const int* __restrict__ dst, int e) {
    int i = blockIdx.x * blockDim.x + threadIdx.x;
    if (i < e) {
        int pos = atomicAdd(&g_fill[dst[i]], 1);
        g_srcs[pos] = src[i];
    }
}

// ---------------------------------------------------------------------------
// GEMM: C[N,128] = A[N,128] @ W[128,128]   (packed f32x2 FMAs, k-grouped loads)
// 256 threads / 64 rows per block. W (64KB) + A tile (32KB) in dynamic smem.
// Thread: lane -> 4 consecutive cols; tid>>5 -> row slot; 8 rows x 4 cols.
// ---------------------------------------------------------------------------
__global__ void gemm128(const float* __restrict__ A, const float* __restrict__ W,
                        float* __restrict__ C, int n) {
    extern __shared__ float sm[];
    float* sW = sm;             // 128*128
    float* sA = sm + 128 * 128; // 64*128

    int tid = threadIdx.x;
    const float4* W4 = reinterpret_cast<const float4*>(W);
    float4* sW4 = reinterpret_cast<float4*>(sW);
#pragma unroll
    for (int i = 0; i < 16; i++) sW4[tid + 256 * i] = W4[tid + 256 * i];

    int row0 = blockIdx.x * 64;
    int nrows = n - row0; if (nrows > 64) nrows = 64;
    const float4* A4 = reinterpret_cast<const float4*>(A + (size_t)row0 * D);
    float4* sA4 = reinterpret_cast<float4*>(sA);
    for (int i = tid; i < nrows * 32; i += 256) sA4[i] = A4[i];
    __syncthreads();

    int lane = tid & 31;
    int rbase = tid >> 5;  // 0..7

    unsigned long long acc0[8], acc1[8];
#pragma unroll
    for (int r = 0; r < 8; r++) { acc0[r] = 0ull; acc1[r] = 0ull; }

#pragma unroll 4
    for (int k4 = 0; k4 < 32; k4++) {
        // 4 W rows for this k-group (lane-strided float4 loads)
        float4 w0 = sW4[(k4 * 4 + 0) * 32 + lane];
        float4 w1 = sW4[(k4 * 4 + 1) * 32 + lane];
        float4 w2 = sW4[(k4 * 4 + 2) * 32 + lane];
        float4 w3 = sW4[(k4 * 4 + 3) * 32 + lane];
        unsigned long long w0xy = pk2(w0.x, w0.y), w0zw = pk2(w0.z, w0.w);
        unsigned long long w1xy = pk2(w1.x, w1.y), w1zw = pk2(w1.z, w1.w);
        unsigned long long w2xy = pk2(w2.x, w2.y), w2zw = pk2(w2.z, w2.w);
        unsigned long long w3xy = pk2(w3.x, w3.y), w3zw = pk2(w3.z, w3.w);
#pragma unroll
        for (int r = 0; r < 8; r++) {
            float4 a = sA4[(rbase + r * 8) * 32 + k4];  // warp-uniform broadcast
            unsigned long long a0 = pk2(a.x, a.x);
            unsigned long long a1 = pk2(a.y, a.y);
            unsigned long long a2 = pk2(a.z, a.z);
            unsigned long long a3 = pk2(a.w, a.w);
            acc0[r] = fma2(a0, w0xy, acc0[r]); acc1[r] = fma2(a0, w0zw, acc1[r]);
            acc0[r] = fma2(a1, w1xy, acc0[r]); acc1[r] = fma2(a1, w1zw, acc1[r]);
            acc0[r] = fma2(a2, w2xy, acc0[r]); acc1[r] = fma2(a2, w2zw, acc1[r]);
            acc0[r] = fma2(a3, w3xy, acc0[r]); acc1[r] = fma2(a3, w3zw, acc1[r]);
        }
    }

    float4* C4 = reinterpret_cast<float4*>(C);
#pragma unroll
    for (int r = 0; r < 8; r++) {
        int rr = rbase + r * 8;
        if (rr < nrows) {
            float2 p0 = upk2(acc0[r]);
            float2 p1 = upk2(acc1[r]);
            float4 v; v.x = p0.x; v.y = p0.y; v.z = p1.x; v.w = p1.y;
            C4[(size_t)(row0 + rr) * 32 + lane] = v;
        }
    }
}

// ---------------------------------------------------------------------------
// CSR aggregation, fused epilogue:
//   a[v] = relu?( dinv[v] * sum_{s in N(v)} dinv[s]*h[s] + dinv[v]^2*h[v] + b )
// One warp per node; lane = one float4 of the 128-wide row.
// Indices staged cooperatively (coalesced load + shfl broadcast) so the
// 128B h-row gathers are independent -> high MLP, L2-throughput-bound.
// ---------------------------------------------------------------------------
__global__ void agg_csr(const float* __restrict__ bias, int n, int relu) {
    int v = (blockIdx.x * blockDim.x + threadIdx.x) >> 5;
    int lane = threadIdx.x & 31;
    if (v >= n) return;
    int beg = g_rowptr[v];
    int end = g_rowptr[v + 1];
    const float4* h4 = reinterpret_cast<const float4*>(g_h);

    float4 acc; acc.x = 0.f; acc.y = 0.f; acc.z = 0.f; acc.w = 0.f;
    for (int j0 = beg; j0 < end; j0 += 32) {
        int idx = j0 + lane;
        int s_l = 0; float w_l = 0.f;
        if (idx < end) {
            s_l = __ldg(&g_srcs[idx]);         // coalesced 32-wide
            w_l = __ldg(&g_dinv[s_l]);
        }
        int m = end - j0; if (m > 32) m = 32;
#pragma unroll 4
        for (int t = 0; t < m; t++) {
            int   s  = __shfl_sync(0xffffffffu, s_l, t);
            float ws = __shfl_sync(0xffffffffu, w_l, t);
            float4 hv = h4[(size_t)s * 32 + lane];   // independent gathers
            acc.x += ws * hv.x; acc.y += ws * hv.y;
            acc.z += ws * hv.z; acc.w += ws * hv.w;
        }
    }

    float dv = g_dinv[v];
    float ss = dv * dv;
    float4 hs = h4[(size_t)v * 32 + lane];
    float4 bb = reinterpret_cast<const float4*>(bias)[lane];
    acc.x = dv * acc.x + ss * hs.x + bb.x;
    acc.y = dv * acc.y + ss * hs.y + bb.y;
    acc.z = dv * acc.z + ss * hs.z + bb.z;
    acc.w = dv * acc.w + ss * hs.w + bb.w;
    if (relu) {
        acc.x = fmaxf(acc.x, 0.f); acc.y = fmaxf(acc.y, 0.f);
        acc.z = fmaxf(acc.z, 0.f); acc.w = fmaxf(acc.w, 0.f);
    }
    reinterpret_cast<float4*>(g_a)[(size_t)v * 32 + lane] = acc;
}

// ---------------------------------------------------------------------------
// Output GEMM: out[N,40] = g_a[N,128] @ Wout[128,40] + bout
// ---------------------------------------------------------------------------
__global__ void gemm_out(const float* __restrict__ W, const float* __restrict__ b,
                         float* __restrict__ C, int n) {
    __shared__ float sW[128 * 40];
    __shared__ float sb[40];
    int tid = threadIdx.x;
    for (int i = tid; i < 128 * 40; i += blockDim.x) sW[i] = W[i];
    if (tid < 40) sb[tid] = b[tid];
    __syncthreads();

    int idx = blockIdx.x * blockDim.x + tid;
    if (idx >= n * 40) return;
    int row = idx / 40;
    int j = idx - row * 40;
    const float4* a4 = reinterpret_cast<const float4*>(g_a) + (size_t)row * 32;
    float acc = sb[j];
#pragma unroll 8
    for (int k4 = 0; k4 < 32; k4++) {
        float4 av = a4[k4];
        int kb = k4 * 4;
        acc += av.x * sW[(kb + 0) * 40 + j];
        acc += av.y * sW[(kb + 1) * 40 + j];
        acc += av.z * sW[(kb + 2) * 40 + j];
        acc += av.w * sW[(kb + 3) * 40 + j];
    }
    C[idx] = acc;
}

// ---------------------------------------------------------------------------
// launch  (gemm128 deliberately placed as the 4th launch: ncu profiles slot 4)
// ---------------------------------------------------------------------------
extern "C" void kernel_launch(void* const* d_in, const int* in_sizes, int n_in,
                              void* d_out, int out_size) {
    const float* x    = (const float*)d_in[0];
    const int*   ei   = (const int*)d_in[1];
    const float* W1   = (const float*)d_in[2];
    const float* b1   = (const float*)d_in[3];
    const float* W2   = (const float*)d_in[4];
    const float* b2   = (const float*)d_in[5];
    const float* Wout = (const float*)d_in[6];
    const float* bout = (const float*)d_in[7];
    float* out = (float*)d_out;

    int n = in_sizes[0] / D;   // 100000
    int e = in_sizes[1] / 2;   // 1600000
    const int* src = ei;
    const int* dst = ei + e;

    static bool attr_set = false;
    if (!attr_set) {
        cudaFuncSetAttribute(gemm128, cudaFuncAttributeMaxDynamicSharedMemorySize,
                             (128 * 128 + 64 * 128) * (int)sizeof(float));
        attr_set = true;
    }
    const int smem_gemm = (128 * 128 + 64 * 128) * (int)sizeof(float);

    float* g_h_ptr; cudaGetSymbolAddress((void**)&g_h_ptr, g_h);
    float* g_a_ptr; cudaGetSymbolAddress((void**)&g_a_ptr, g_a);

    const int tb = 256;
    int nb_n = (n + tb - 1) / tb;
    int nb_e = (e + tb - 1) / tb;
    int gemm_blocks = (n + 63) / 64;
    int agg_blocks  = (n + 7) / 8;   // 8 warps (nodes) per block

    // ---- CSR build + layer-1 GEMM interleaved ----
    zero_deg<<<nb_n, tb>>>(n);                         // 1
    deg_hist<<<nb_e, tb>>>(dst, e);                    // 2
    scan_rowptr<<<1, 1024>>>(n);                       // 3 (rowptr + fill + dinv)
    gemm128<<<gemm_blocks, tb, smem_gemm>>>(x, W1, g_h_ptr, n);   // 4  <- profiled
    scatter_edges<<<nb_e, tb>>>(src, dst, e);          // 5

    // ---- layer 1 aggregate: a = relu(Ahat h + b1) ----
    agg_csr<<<agg_blocks, tb>>>(b1, n, 1);             // 6

    // ---- layer 2 ----
    gemm128<<<gemm_blocks, tb, smem_gemm>>>(g_a_ptr, W2, g_h_ptr, n);  // 7
    agg_csr<<<agg_blocks, tb>>>(b2, n, 0);             // 8

    // ---- output: out = a@Wout + bout ----
    gemm_out<<<(n * 40 + tb - 1) / tb, tb>>>(Wout, bout, out, n);      // 9
}